// round 1
// baseline (speedup 1.0000x reference)
#include <cuda_runtime.h>
#include <cuda_bf16.h>

#define FEAT 128
#define NMAX 131072
#define FULLMASK 0xffffffffu

// ---- device scratch (no allocations allowed) ----
__device__ int   g_cnt[NMAX];
__device__ float g_rcnt[NMAX];
__device__ float g_u[NMAX];
__device__ float g_meanx[FEAT];
__device__ float g_B[FEAT];
__device__ float g_A[FEAT];
__device__ float g_Sw;
__device__ int   g_is64;

// ---------------------------------------------------------------------------
// K0: zero scratch + detect whether edge_index is int64 or int32.
// For int64 values < 2^31 (src/dst < 1e5), every odd 32-bit word is 0.
// For genuine int32 data (random in [0,1e5)), P(128 consecutive zeros) ~ 0.
// ---------------------------------------------------------------------------
__global__ void k_init(const void* __restrict__ edge, int N) {
    int i = blockIdx.x * blockDim.x + threadIdx.x;
    if (i < N) { g_cnt[i] = 0; g_u[i] = 0.f; }
    if (blockIdx.x == 0) {
        if (threadIdx.x < FEAT) {
            g_meanx[threadIdx.x] = 0.f;
            g_B[threadIdx.x] = 0.f;
            g_A[threadIdx.x] = 0.f;
        }
        if (threadIdx.x == 0) {
            g_Sw = 0.f;
            const int* w = (const int*)edge;
            int is64 = 1;
            #pragma unroll 1
            for (int k = 0; k < 64; k++) {
                if (w[2 * k + 1] != 0) { is64 = 0; break; }
            }
            g_is64 = is64;
        }
    }
}

// K1: in-degree count: cnt[dst]++ per edge.
__global__ void k_count(const void* __restrict__ edge, int E) {
    const int is64 = g_is64;
    const long long* e64 = (const long long*)edge;
    const int* e32 = (const int*)edge;
    for (int e = blockIdx.x * blockDim.x + threadIdx.x; e < E;
         e += gridDim.x * blockDim.x) {
        int d = is64 ? (int)e64[(long long)E + e] : e32[E + e];
        atomicAdd(&g_cnt[d], 1);
    }
}

// K2: rcnt = 1/max(cnt,1); Sw = #nodes with cnt>0 (exact).
__global__ void k_rcnt(int N) {
    int i = blockIdx.x * blockDim.x + threadIdx.x;
    int nz = 0;
    if (i < N) {
        int c = g_cnt[i];
        g_rcnt[i] = 1.0f / (float)max(c, 1);
        nz = (c > 0) ? 1 : 0;
    }
    unsigned b = __ballot_sync(FULLMASK, nz);
    if ((threadIdx.x & 31) == 0 && b)
        atomicAdd(&g_Sw, (float)__popc(b));
}

// K3: column sums of x -> g_meanx (divide by N later).
__global__ void k_colsum(const float* __restrict__ x, int N) {
    int c = threadIdx.x;  // 128 threads per block
    long long stride = (long long)gridDim.x;
    float a0 = 0.f, a1 = 0.f, a2 = 0.f, a3 = 0.f;
    long long r = blockIdx.x;
    for (; r + 3 * stride < N; r += 4 * stride) {
        a0 += x[r * FEAT + c];
        a1 += x[(r + stride) * FEAT + c];
        a2 += x[(r + 2 * stride) * FEAT + c];
        a3 += x[(r + 3 * stride) * FEAT + c];
    }
    for (; r < N; r += stride) a0 += x[r * FEAT + c];
    atomicAdd(&g_meanx[c], (a0 + a1) + (a2 + a3));
}

// K4: u[src] += 1/cnt[dst] per edge.
__global__ void k_u(const void* __restrict__ edge, int E) {
    const int is64 = g_is64;
    const long long* e64 = (const long long*)edge;
    const int* e32 = (const int*)edge;
    for (int e = blockIdx.x * blockDim.x + threadIdx.x; e < E;
         e += gridDim.x * blockDim.x) {
        int s, d;
        if (is64) { s = (int)e64[e]; d = (int)e64[(long long)E + e]; }
        else      { s = e32[e];      d = e32[E + e]; }
        atomicAdd(&g_u[s], g_rcnt[d]);
    }
}

// K5: the heavy pass. One warp handles 32 edges per chunk:
//   coalesced load of 32 (src,dst), gather rcnt[dst], u[dst],
//   then 32 sub-iterations: broadcast scalars via shfl, each lane reads one
//   float4 of x[src] (512B/warp, coalesced) and FMAs into two accumulators:
//     B += (1/cnt_d) * x[src],   A += (u_d/cnt_d) * x[src]
__global__ void k_edge_acc(const void* __restrict__ edge,
                           const float* __restrict__ x, int E) {
    const int is64 = g_is64;
    const int lane = threadIdx.x & 31;
    const int warp = (blockIdx.x * blockDim.x + threadIdx.x) >> 5;
    const int nwarps = (gridDim.x * blockDim.x) >> 5;
    const long long* e64 = (const long long*)edge;
    const int* e32 = (const int*)edge;

    float4 aB = make_float4(0.f, 0.f, 0.f, 0.f);
    float4 aA = make_float4(0.f, 0.f, 0.f, 0.f);

    for (int base = warp * 32; base < E; base += nwarps * 32) {
        int e = base + lane;
        int s = 0; float rc = 0.f, s2 = 0.f;
        if (e < E) {
            int d;
            if (is64) { s = (int)e64[e]; d = (int)e64[(long long)E + e]; }
            else      { s = e32[e];      d = e32[E + e]; }
            rc = __ldg(&g_rcnt[d]);
            s2 = __ldg(&g_u[d]) * rc;
        }
        int m = min(32, E - base);
        if (m == 32) {
            #pragma unroll 8
            for (int k = 0; k < 32; k++) {
                int   sk  = __shfl_sync(FULLMASK, s,  k);
                float rck = __shfl_sync(FULLMASK, rc, k);
                float s2k = __shfl_sync(FULLMASK, s2, k);
                float4 xv = *(const float4*)(x + (long long)sk * FEAT + lane * 4);
                aB.x = fmaf(rck, xv.x, aB.x); aB.y = fmaf(rck, xv.y, aB.y);
                aB.z = fmaf(rck, xv.z, aB.z); aB.w = fmaf(rck, xv.w, aB.w);
                aA.x = fmaf(s2k, xv.x, aA.x); aA.y = fmaf(s2k, xv.y, aA.y);
                aA.z = fmaf(s2k, xv.z, aA.z); aA.w = fmaf(s2k, xv.w, aA.w);
            }
        } else {
            for (int k = 0; k < m; k++) {
                int   sk  = __shfl_sync(FULLMASK, s,  k);
                float rck = __shfl_sync(FULLMASK, rc, k);
                float s2k = __shfl_sync(FULLMASK, s2, k);
                float4 xv = *(const float4*)(x + (long long)sk * FEAT + lane * 4);
                aB.x = fmaf(rck, xv.x, aB.x); aB.y = fmaf(rck, xv.y, aB.y);
                aB.z = fmaf(rck, xv.z, aB.z); aB.w = fmaf(rck, xv.w, aB.w);
                aA.x = fmaf(s2k, xv.x, aA.x); aA.y = fmaf(s2k, xv.y, aA.y);
                aA.z = fmaf(s2k, xv.z, aA.z); aA.w = fmaf(s2k, xv.w, aA.w);
            }
        }
    }

    // block-level reduction, then one global atomicAdd set per block
    __shared__ float sB[FEAT], sA[FEAT];
    if (threadIdx.x < FEAT) { sB[threadIdx.x] = 0.f; sA[threadIdx.x] = 0.f; }
    __syncthreads();
    int c = lane * 4;
    atomicAdd(&sB[c + 0], aB.x); atomicAdd(&sB[c + 1], aB.y);
    atomicAdd(&sB[c + 2], aB.z); atomicAdd(&sB[c + 3], aB.w);
    atomicAdd(&sA[c + 0], aA.x); atomicAdd(&sA[c + 1], aA.y);
    atomicAdd(&sA[c + 2], aA.z); atomicAdd(&sA[c + 3], aA.w);
    __syncthreads();
    if (threadIdx.x < FEAT) {
        atomicAdd(&g_B[threadIdx.x], sB[threadIdx.x]);
        atomicAdd(&g_A[threadIdx.x], sA[threadIdx.x]);
    }
}

// K6: tiny final combine, single block of 128 threads.
//   mean_h1 = (B/N)@W1_l + (meanx/N)@W1_r + b1
//   v1      = A@W1_l + B@W1_r + Sw*b1 ;  mean_agg2 = v1/N
//   g       = mean_agg2@W2_l + mean_h1@W2_r + b2
//   out     = g@W_out + b_out
__global__ void k_final(const float* __restrict__ W1l, const float* __restrict__ W1r,
                        const float* __restrict__ b1,
                        const float* __restrict__ W2l, const float* __restrict__ W2r,
                        const float* __restrict__ b2,
                        const float* __restrict__ Wout, const float* __restrict__ bout,
                        float* __restrict__ out, int N, int C) {
    __shared__ float s_ma1[FEAT], s_mx[FEAT], s_A[FEAT], s_B[FEAT];
    __shared__ float s_mh1[FEAT], s_ma2[FEAT], s_g[FEAT];
    int t = threadIdx.x;
    float invN = 1.0f / (float)N;
    float Sw = g_Sw;
    s_B[t]  = g_B[t];
    s_A[t]  = g_A[t];
    s_ma1[t] = g_B[t] * invN;
    s_mx[t]  = g_meanx[t] * invN;
    __syncthreads();

    float mh = b1[t];
    float v1 = Sw * b1[t];
    #pragma unroll 8
    for (int k = 0; k < FEAT; k++) {
        float wl = W1l[k * FEAT + t];
        float wr = W1r[k * FEAT + t];
        mh = fmaf(s_ma1[k], wl, mh);
        mh = fmaf(s_mx[k],  wr, mh);
        v1 = fmaf(s_A[k],   wl, v1);
        v1 = fmaf(s_B[k],   wr, v1);
    }
    s_mh1[t] = mh;
    s_ma2[t] = v1 * invN;
    __syncthreads();

    float gv = b2[t];
    #pragma unroll 8
    for (int k = 0; k < FEAT; k++) {
        gv = fmaf(s_ma2[k], W2l[k * FEAT + t], gv);
        gv = fmaf(s_mh1[k], W2r[k * FEAT + t], gv);
    }
    s_g[t] = gv;
    __syncthreads();

    if (t < C) {
        float acc = bout[t];
        #pragma unroll 8
        for (int k = 0; k < FEAT; k++)
            acc = fmaf(s_g[k], Wout[k * C + t], acc);
        out[t] = acc;
    }
}

extern "C" void kernel_launch(void* const* d_in, const int* in_sizes, int n_in,
                              void* d_out, int out_size) {
    const float* x    = (const float*)d_in[0];
    const void*  edge = d_in[1];
    const float* W1l  = (const float*)d_in[2];
    const float* W1r  = (const float*)d_in[3];
    const float* b1   = (const float*)d_in[4];
    const float* W2l  = (const float*)d_in[5];
    const float* W2r  = (const float*)d_in[6];
    const float* b2   = (const float*)d_in[7];
    const float* Wout = (const float*)d_in[8];
    const float* bout = (const float*)d_in[9];
    float* out = (float*)d_out;

    int N = in_sizes[0] / FEAT;
    int E = in_sizes[1] / 2;
    int C = out_size;

    int nblk = (N + 255) / 256;
    k_init <<<nblk, 256>>>(edge, N);
    k_count<<<1184, 256>>>(edge, E);
    k_rcnt <<<nblk, 256>>>(N);
    k_colsum<<<1024, 128>>>(x, N);
    k_u    <<<1184, 256>>>(edge, E);
    k_edge_acc<<<1184, 256>>>(edge, x, E);
    k_final<<<1, 128>>>(W1l, W1r, b1, W2l, W2r, b2, Wout, bout, out, N, C);
}

// round 3
// speedup vs baseline: 1.4725x; 1.4725x over previous
#include <cuda_runtime.h>
#include <cuda_bf16.h>

#define FEAT 128
#define NMAX 131072
#define FULLMASK 0xffffffffu

// ---- device scratch (no allocations allowed) ----
__device__ int   g_cnt[NMAX];
__device__ float g_rcnt[NMAX];
__device__ float g_u[NMAX];     // u_j = sum_{e: src=j} 1/cnt[dst_e]
__device__ float g_t[NMAX];     // t_j = u_j * rcnt_j
__device__ float g_v[NMAX];     // v_j = sum_{e: src=j} t[dst_e]
__device__ float g_meanx[FEAT]; // column sums of x (divide by N later)
__device__ float g_B[FEAT];     // B = sum_j u_j x_j
__device__ float g_A[FEAT];     // A = sum_j v_j x_j
__device__ float g_Sw;
__device__ int   g_is64;

// ---------------------------------------------------------------------------
// K0: zero scratch + detect int64 vs int32 edge_index.
// ---------------------------------------------------------------------------
__global__ void k_init(const void* __restrict__ edge, int N) {
    int i = blockIdx.x * blockDim.x + threadIdx.x;
    if (i < N) { g_cnt[i] = 0; g_u[i] = 0.f; g_v[i] = 0.f; }
    if (blockIdx.x == 0) {
        if (threadIdx.x < FEAT) {
            g_meanx[threadIdx.x] = 0.f;
            g_B[threadIdx.x] = 0.f;
            g_A[threadIdx.x] = 0.f;
        }
        if (threadIdx.x == 0) {
            g_Sw = 0.f;
            const int* w = (const int*)edge;
            int is64 = 1;
            #pragma unroll 1
            for (int k = 0; k < 64; k++) {
                if (w[2 * k + 1] != 0) { is64 = 0; break; }
            }
            g_is64 = is64;
        }
    }
}

// K1: in-degree count: cnt[dst]++ per edge.
__global__ void k_count(const void* __restrict__ edge, int E) {
    const int is64 = g_is64;
    const long long* e64 = (const long long*)edge;
    const int* e32 = (const int*)edge;
    for (int e = blockIdx.x * blockDim.x + threadIdx.x; e < E;
         e += gridDim.x * blockDim.x) {
        int d = is64 ? (int)e64[(long long)E + e] : e32[E + e];
        atomicAdd(&g_cnt[d], 1);
    }
}

// K2: rcnt = 1/max(cnt,1); Sw = #nodes with cnt>0.
__global__ void k_rcnt(int N) {
    int i = blockIdx.x * blockDim.x + threadIdx.x;
    int nz = 0;
    if (i < N) {
        int c = g_cnt[i];
        g_rcnt[i] = 1.0f / (float)max(c, 1);
        nz = (c > 0) ? 1 : 0;
    }
    unsigned b = __ballot_sync(FULLMASK, nz);
    if ((threadIdx.x & 31) == 0 && b)
        atomicAdd(&g_Sw, (float)__popc(b));
}

// K3: u[src] += rcnt[dst] per edge.
__global__ void k_u(const void* __restrict__ edge, int E) {
    const int is64 = g_is64;
    const long long* e64 = (const long long*)edge;
    const int* e32 = (const int*)edge;
    for (int e = blockIdx.x * blockDim.x + threadIdx.x; e < E;
         e += gridDim.x * blockDim.x) {
        int s, d;
        if (is64) { s = (int)e64[e]; d = (int)e64[(long long)E + e]; }
        else      { s = e32[e];      d = e32[E + e]; }
        atomicAdd(&g_u[s], __ldg(&g_rcnt[d]));
    }
}

// K4: t = u * rcnt (per node, tiny).
__global__ void k_t(int N) {
    int i = blockIdx.x * blockDim.x + threadIdx.x;
    if (i < N) g_t[i] = g_u[i] * g_rcnt[i];
}

// K5: v[src] += t[dst] per edge.
__global__ void k_v(const void* __restrict__ edge, int E) {
    const int is64 = g_is64;
    const long long* e64 = (const long long*)edge;
    const int* e32 = (const int*)edge;
    for (int e = blockIdx.x * blockDim.x + threadIdx.x; e < E;
         e += gridDim.x * blockDim.x) {
        int s, d;
        if (is64) { s = (int)e64[e]; d = (int)e64[(long long)E + e]; }
        else      { s = e32[e];      d = e32[E + e]; }
        atomicAdd(&g_v[s], __ldg(&g_t[d]));
    }
}

// K6: single weighted pass over x: one warp per row.
//   meanx += x[j];  B += u_j * x[j];  A += v_j * x[j]
// Lane L accumulates columns [4L, 4L+4) as a float4. 512B/row coalesced.
__global__ void k_xpass(const float* __restrict__ x, int N) {
    const int lane = threadIdx.x & 31;
    const int warp = (blockIdx.x * blockDim.x + threadIdx.x) >> 5;
    const int nwarps = (gridDim.x * blockDim.x) >> 5;

    float4 amx = make_float4(0.f, 0.f, 0.f, 0.f);
    float4 aB  = make_float4(0.f, 0.f, 0.f, 0.f);
    float4 aA  = make_float4(0.f, 0.f, 0.f, 0.f);

    #pragma unroll 2
    for (int r = warp; r < N; r += nwarps) {
        float uj = __ldg(&g_u[r]);
        float vj = __ldg(&g_v[r]);
        float4 xv = *(const float4*)(x + (long long)r * FEAT + lane * 4);
        amx.x += xv.x; amx.y += xv.y; amx.z += xv.z; amx.w += xv.w;
        aB.x = fmaf(uj, xv.x, aB.x); aB.y = fmaf(uj, xv.y, aB.y);
        aB.z = fmaf(uj, xv.z, aB.z); aB.w = fmaf(uj, xv.w, aB.w);
        aA.x = fmaf(vj, xv.x, aA.x); aA.y = fmaf(vj, xv.y, aA.y);
        aA.z = fmaf(vj, xv.z, aA.z); aA.w = fmaf(vj, xv.w, aA.w);
    }

    __shared__ float smx[FEAT], sB[FEAT], sA[FEAT];
    if (threadIdx.x < FEAT) { smx[threadIdx.x] = 0.f; sB[threadIdx.x] = 0.f; sA[threadIdx.x] = 0.f; }
    __syncthreads();
    int c = lane * 4;
    atomicAdd(&smx[c + 0], amx.x); atomicAdd(&smx[c + 1], amx.y);
    atomicAdd(&smx[c + 2], amx.z); atomicAdd(&smx[c + 3], amx.w);
    atomicAdd(&sB[c + 0], aB.x);   atomicAdd(&sB[c + 1], aB.y);
    atomicAdd(&sB[c + 2], aB.z);   atomicAdd(&sB[c + 3], aB.w);
    atomicAdd(&sA[c + 0], aA.x);   atomicAdd(&sA[c + 1], aA.y);
    atomicAdd(&sA[c + 2], aA.z);   atomicAdd(&sA[c + 3], aA.w);
    __syncthreads();
    if (threadIdx.x < FEAT) {
        atomicAdd(&g_meanx[threadIdx.x], smx[threadIdx.x]);
        atomicAdd(&g_B[threadIdx.x], sB[threadIdx.x]);
        atomicAdd(&g_A[threadIdx.x], sA[threadIdx.x]);
    }
}

// K7: tiny final combine, single block of 128 threads.
//   mean_h1  = (B/N)@W1_l + (meanx/N)@W1_r + b1
//   v1       = A@W1_l + B@W1_r + Sw*b1 ;  mean_agg2 = v1/N
//   g        = mean_agg2@W2_l + mean_h1@W2_r + b2
//   out      = g@W_out + b_out
__global__ void k_final(const float* __restrict__ W1l, const float* __restrict__ W1r,
                        const float* __restrict__ b1,
                        const float* __restrict__ W2l, const float* __restrict__ W2r,
                        const float* __restrict__ b2,
                        const float* __restrict__ Wout, const float* __restrict__ bout,
                        float* __restrict__ out, int N, int C) {
    __shared__ float s_ma1[FEAT], s_mx[FEAT], s_A[FEAT], s_B[FEAT];
    __shared__ float s_mh1[FEAT], s_ma2[FEAT], s_g[FEAT];
    int t = threadIdx.x;
    float invN = 1.0f / (float)N;
    float Sw = g_Sw;
    s_B[t]  = g_B[t];
    s_A[t]  = g_A[t];
    s_ma1[t] = g_B[t] * invN;
    s_mx[t]  = g_meanx[t] * invN;
    __syncthreads();

    float mh = b1[t];
    float v1 = Sw * b1[t];
    #pragma unroll 8
    for (int k = 0; k < FEAT; k++) {
        float wl = W1l[k * FEAT + t];
        float wr = W1r[k * FEAT + t];
        mh = fmaf(s_ma1[k], wl, mh);
        mh = fmaf(s_mx[k],  wr, mh);
        v1 = fmaf(s_A[k],   wl, v1);
        v1 = fmaf(s_B[k],   wr, v1);
    }
    s_mh1[t] = mh;
    s_ma2[t] = v1 * invN;
    __syncthreads();

    float gv = b2[t];
    #pragma unroll 8
    for (int k = 0; k < FEAT; k++) {
        gv = fmaf(s_ma2[k], W2l[k * FEAT + t], gv);
        gv = fmaf(s_mh1[k], W2r[k * FEAT + t], gv);
    }
    s_g[t] = gv;
    __syncthreads();

    if (t < C) {
        float acc = bout[t];
        #pragma unroll 8
        for (int k = 0; k < FEAT; k++)
            acc = fmaf(s_g[k], Wout[k * C + t], acc);
        out[t] = acc;
    }
}

extern "C" void kernel_launch(void* const* d_in, const int* in_sizes, int n_in,
                              void* d_out, int out_size) {
    const float* x    = (const float*)d_in[0];
    const void*  edge = d_in[1];
    const float* W1l  = (const float*)d_in[2];
    const float* W1r  = (const float*)d_in[3];
    const float* b1   = (const float*)d_in[4];
    const float* W2l  = (const float*)d_in[5];
    const float* W2r  = (const float*)d_in[6];
    const float* b2   = (const float*)d_in[7];
    const float* Wout = (const float*)d_in[8];
    const float* bout = (const float*)d_in[9];
    float* out = (float*)d_out;

    int N = in_sizes[0] / FEAT;
    int E = in_sizes[1] / 2;
    int C = out_size;

    int nblk = (N + 255) / 256;
    k_init <<<nblk, 256>>>(edge, N);
    k_count<<<1184, 256>>>(edge, E);
    k_rcnt <<<nblk, 256>>>(N);
    k_u    <<<1184, 256>>>(edge, E);
    k_t    <<<nblk, 256>>>(N);
    k_v    <<<1184, 256>>>(edge, E);
    k_xpass<<<1184, 256>>>(x, N);
    k_final<<<1, 128>>>(W1l, W1r, b1, W2l, W2r, b2, Wout, bout, out, N, C);
}